// round 5
// baseline (speedup 1.0000x reference)
#include <cuda_runtime.h>
#include <cstdint>

#define B_SZ 64
#define NS   16
#define SD   256
#define FS   4096

// scratch (no allocations allowed): S = slots@W1 (1 MB), P = pos@W1 + b1 (4 MB), idx (1 MB)
static __device__ float g_S[B_SZ * NS * SD];
static __device__ float g_P[FS * SD];
static __device__ int   g_idx[B_SZ * FS];

__device__ __forceinline__ uint32_t f2tf32(float x) {
    uint32_t r;
    asm("cvt.rna.tf32.f32 %0, %1;" : "=r"(r) : "f"(x));
    return r;
}

__device__ __forceinline__ void mma_tf32(float* c, const uint32_t* a, uint2 b) {
    asm volatile(
        "mma.sync.aligned.m16n8k8.row.col.f32.tf32.tf32.f32 "
        "{%0,%1,%2,%3}, {%4,%5,%6,%7}, {%8,%9}, {%0,%1,%2,%3};"
        : "+f"(c[0]), "+f"(c[1]), "+f"(c[2]), "+f"(c[3])
        : "r"(a[0]), "r"(a[1]), "r"(a[2]), "r"(a[3]), "r"(b.x), "r"(b.y));
}

// ---------------------------------------------------------------------------
// K1: argmax over slot axis. mask[b, s, f] -> idx[b, f] (first max, matches jnp)
// ---------------------------------------------------------------------------
__global__ void k_argmax(const float* __restrict__ mask) {
    int t = blockIdx.x * blockDim.x + threadIdx.x;   // B*FS threads
    int b = t >> 12, f = t & (FS - 1);
    const float* mp = mask + (size_t)b * NS * FS + f;
    float best = mp[0];
    int bi = 0;
#pragma unroll
    for (int s = 1; s < NS; s++) {
        float v = mp[(size_t)s * FS];
        if (v > best) { best = v; bi = s; }
    }
    g_idx[t] = bi;
}

// ---------------------------------------------------------------------------
// K2: fused small GEMM, fp32 exact.
//   rows [0,1024):    g_S[m]      = slots[m]      @ W1
//   rows [1024,5120): g_P[m-1024] = pos[m-1024]   @ W1 + b1
// 64x64 CTA tile, 256 threads, 4x4 microtile, k-chunk 16.
// ---------------------------------------------------------------------------
__global__ void __launch_bounds__(256) k_pre(const float* __restrict__ slots,
                                             const float* __restrict__ pos,
                                             const float* __restrict__ W1,
                                             const float* __restrict__ b1) {
    __shared__ float As[16][68];   // [k][m], padded
    __shared__ float Bs[16][68];   // [k][n], padded

    const int tid = threadIdx.x;
    const int m0 = blockIdx.x * 64, n0 = blockIdx.y * 64;
    const int tx = tid & 15, ty = tid >> 4;

    const int lm = tid >> 2, kq = tid & 3;          // A loader mapping
    const int bk = tid >> 4, bn = tid & 15;         // B loader mapping
    const int rm = m0 + lm;
    const float* arow = (rm < 1024) ? (slots + (size_t)rm * SD)
                                    : (pos + (size_t)(rm - 1024) * SD);

    float acc[4][4] = {};

    for (int kc = 0; kc < 16; kc++) {
        const int k0 = kc * 16;
        float4 av = *(const float4*)(arow + k0 + kq * 4);
        float4 bv = *(const float4*)(W1 + (size_t)(k0 + bk) * SD + n0 + bn * 4);
        __syncthreads();
        As[kq * 4 + 0][lm] = av.x;
        As[kq * 4 + 1][lm] = av.y;
        As[kq * 4 + 2][lm] = av.z;
        As[kq * 4 + 3][lm] = av.w;
        *(float4*)&Bs[bk][bn * 4] = bv;
        __syncthreads();
#pragma unroll
        for (int kk = 0; kk < 16; kk++) {
            float4 a4 = *(const float4*)&As[kk][ty * 4];
            float4 b4 = *(const float4*)&Bs[kk][tx * 4];
            float aa[4] = {a4.x, a4.y, a4.z, a4.w};
            float bb[4] = {b4.x, b4.y, b4.z, b4.w};
#pragma unroll
            for (int i = 0; i < 4; i++)
#pragma unroll
                for (int j = 0; j < 4; j++) acc[i][j] += aa[i] * bb[j];
        }
    }

    float4 b1v = *(const float4*)(b1 + n0 + tx * 4);
    float badd[4] = {b1v.x, b1v.y, b1v.z, b1v.w};
#pragma unroll
    for (int i = 0; i < 4; i++) {
        int m = m0 + ty * 4 + i;
        if (m < 1024) {
            float4 v = make_float4(acc[i][0], acc[i][1], acc[i][2], acc[i][3]);
            *(float4*)(g_S + (size_t)m * SD + n0 + tx * 4) = v;
        } else {
            float4 v = make_float4(acc[i][0] + badd[0], acc[i][1] + badd[1],
                                   acc[i][2] + badd[2], acc[i][3] + badd[3]);
            *(float4*)(g_P + (size_t)(m - 1024) * SD + n0 + tx * 4) = v;
        }
    }
}

// ---------------------------------------------------------------------------
// K3: fused gather + ReLU + GEMM2 (tf32 mma.sync m16n8k8).
// CTA = 128(M=f) x 128(N), 8 warps as 4(M) x 2(N), warp tile 32x64, K=256 in
// 8 stages of 32. A built on the fly: relu(S[b, idx[f], k] + P[f, k]).
// A_sm / B_sm stored in mma-fragment-native order (vector LDS, no ldmatrix).
// ---------------------------------------------------------------------------
__global__ void __launch_bounds__(256, 2) k_main(const float* __restrict__ W2,
                                                 const float* __restrict__ b2,
                                                 float* __restrict__ out) {
    // A frag layout: [slot(4)][mi(8)][ks(4)][lane pad 33]
    __shared__ uint32_t A_sm[4 * 8 * 4 * 33];
    // B frag layout: [ni(16)][ks(4)][lane*2 pad 66]
    __shared__ uint32_t B_sm[16 * 4 * 66];
    __shared__ float    C_sm[16][36];     // S slice for this k-stage (16 slot rows)
    __shared__ int      idx_sm[128];
    __shared__ float    b2_sm[130];

    const int tid  = threadIdx.x;
    const int lane = tid & 31, wid = tid >> 5;
    const int wm = wid & 3, wn = wid >> 2;            // 4 x 2 warp grid
    const int nt = blockIdx.x, ft = blockIdx.y, b = blockIdx.z;
    const int f0 = ft * 128, n0 = nt * 128;

    if (tid < 128) {
        idx_sm[tid] = g_idx[b * FS + f0 + tid];
        b2_sm[tid]  = b2[n0 + tid];
    }

    const float* Sb = g_S + (size_t)b * NS * SD;

    float c[2][8][4];
#pragma unroll
    for (int m = 0; m < 2; m++)
#pragma unroll
        for (int n = 0; n < 8; n++)
#pragma unroll
            for (int k = 0; k < 4; k++) c[m][n][k] = 0.f;

    const int bn_ = tid & 127, bq_ = tid >> 7;

#pragma unroll 1
    for (int kt = 0; kt < 8; kt++) {
        const int k0 = kt * 32;
        __syncthreads();   // previous stage's mma done reading A_sm/B_sm/C_sm

        // S slice for this stage: 16 rows x 32 cols
        if (tid < 128) {
            int i = tid >> 3, cq = tid & 7;
            *(float4*)&C_sm[i][cq * 4] =
                *(const float4*)(Sb + i * SD + k0 + cq * 4);
        }

        // B build: W2 slice [32 x 128] -> fragment order (cvt to tf32)
#pragma unroll
        for (int j = 0; j < 8; j++) {
            int v = bq_ * 8 + j, ks = v >> 2, kk = v & 3;
            int krow = k0 + ks * 8 + kk;
            uint32_t w0 = f2tf32(W2[(size_t)krow * SD + n0 + bn_]);
            uint32_t w1 = f2tf32(W2[(size_t)(krow + 4) * SD + n0 + bn_]);
            int ni = bn_ >> 3, ln = (bn_ & 7) * 4 + kk;
            *(uint2*)&B_sm[(ni * 4 + ks) * 66 + ln * 2] = make_uint2(w0, w1);
        }
        __syncthreads();   // C_sm ready

        // A build: relu(S[idx] + P) -> tf32 -> fragment order
#pragma unroll
        for (int u = 0; u < 4; u++) {
            int id = tid + 256 * u;
            int cg = id & 7, r = id >> 3;            // col-group, row in tile
            int irow = idx_sm[r];
            float4 p  = *(const float4*)(g_P + (size_t)(f0 + r) * SD + k0 + cg * 4);
            float4 cv = *(const float4*)&C_sm[irow][cg * 4];
            int rr = r & 15, mi = r >> 4;
            int g = rr & 7, rhi = rr >> 3;
            int ks = cg >> 1, hi = cg & 1;
            int base = (((rhi + 2 * hi) * 8 + mi) * 4 + ks) * 33 + g * 4;
            A_sm[base + 0] = f2tf32(fmaxf(cv.x + p.x, 0.f));
            A_sm[base + 1] = f2tf32(fmaxf(cv.y + p.y, 0.f));
            A_sm[base + 2] = f2tf32(fmaxf(cv.z + p.z, 0.f));
            A_sm[base + 3] = f2tf32(fmaxf(cv.w + p.w, 0.f));
        }
        __syncthreads();   // A_sm / B_sm ready

        // MMA: 4 k-subtiles of 8
#pragma unroll
        for (int ks = 0; ks < 4; ks++) {
            uint32_t a[2][4];
#pragma unroll
            for (int m = 0; m < 2; m++) {
                int mi = wm * 2 + m;
#pragma unroll
                for (int s = 0; s < 4; s++)
                    a[m][s] = A_sm[((s * 8 + mi) * 4 + ks) * 33 + lane];
            }
#pragma unroll
            for (int nf = 0; nf < 8; nf++) {
                int ni = wn * 8 + nf;
                uint2 bb = *(const uint2*)&B_sm[(ni * 4 + ks) * 66 + lane * 2];
                mma_tf32(c[0][nf], a[0], bb);
                mma_tf32(c[1][nf], a[1], bb);
            }
        }
    }

    // epilogue: add b2, store fp32 (full 32B sectors via float2)
    const int g = lane >> 2, cc = (lane & 3) * 2;
#pragma unroll
    for (int m = 0; m < 2; m++) {
        int rbase = f0 + wm * 32 + m * 16 + g;
#pragma unroll
        for (int nf = 0; nf < 8; nf++) {
            int coll = wn * 64 + nf * 8 + cc;
            float bx = b2_sm[coll], by = b2_sm[coll + 1];
            size_t o0 = ((size_t)(b * FS + rbase)) * SD + n0 + coll;
            size_t o1 = ((size_t)(b * FS + rbase + 8)) * SD + n0 + coll;
            *(float2*)(out + o0) = make_float2(c[m][nf][0] + bx, c[m][nf][1] + by);
            *(float2*)(out + o1) = make_float2(c[m][nf][2] + bx, c[m][nf][3] + by);
        }
    }
}

// ---------------------------------------------------------------------------
extern "C" void kernel_launch(void* const* d_in, const int* in_sizes, int n_in,
                              void* d_out, int out_size) {
    const float* slots = (const float*)d_in[0];
    const float* mask  = (const float*)d_in[1];
    const float* pos   = (const float*)d_in[2];
    const float* W1    = (const float*)d_in[3];
    const float* b1    = (const float*)d_in[4];
    const float* W2    = (const float*)d_in[5];
    const float* b2    = (const float*)d_in[6];
    float* out = (float*)d_out;

    k_argmax<<<(B_SZ * FS) / 256, 256>>>(mask);
    k_pre<<<dim3(80, 4), 256>>>(slots, pos, W1, b1);
    k_main<<<dim3(2, 32, 64), 256>>>(W2, b2, out);
}

// round 9
// speedup vs baseline: 1.8197x; 1.8197x over previous
#include <cuda_runtime.h>
#include <cuda_fp16.h>
#include <cstdint>

#define B_SZ 64
#define NS   16
#define SD   256
#define FS   4096

// scratch: S = slots@W1 (1MB), P = pos@W1 + b1 (4MB), idx (1MB), W2^T half (128KB)
static __device__ float  g_S[B_SZ * NS * SD];
static __device__ float  g_P[FS * SD];
static __device__ int    g_idx[B_SZ * FS];
static __device__ __half g_W2h[SD * SD];   // [n][k]

__device__ __forceinline__ void mma_f16(float* c, const uint32_t* a, uint32_t b0, uint32_t b1) {
    asm volatile(
        "mma.sync.aligned.m16n8k16.row.col.f32.f16.f16.f32 "
        "{%0,%1,%2,%3}, {%4,%5,%6,%7}, {%8,%9}, {%0,%1,%2,%3};"
        : "+f"(c[0]), "+f"(c[1]), "+f"(c[2]), "+f"(c[3])
        : "r"(a[0]), "r"(a[1]), "r"(a[2]), "r"(a[3]), "r"(b0), "r"(b1));
}

// ---------------------------------------------------------------------------
// K1: argmax over slot axis. mask[b, s, f] -> idx[b, f] (first max, matches jnp)
// ---------------------------------------------------------------------------
__global__ void k_argmax(const float* __restrict__ mask) {
    int t = blockIdx.x * blockDim.x + threadIdx.x;
    int b = t >> 12, f = t & (FS - 1);
    const float* mp = mask + (size_t)b * NS * FS + f;
    float best = mp[0];
    int bi = 0;
#pragma unroll
    for (int s = 1; s < NS; s++) {
        float v = mp[(size_t)s * FS];
        if (v > best) { best = v; bi = s; }
    }
    g_idx[t] = bi;
}

// ---------------------------------------------------------------------------
// K2: S = slots@W1 ; P = pos@W1 + b1  (fp32 exact, 64x64 tiles)
// ---------------------------------------------------------------------------
__global__ void __launch_bounds__(256) k_pre(const float* __restrict__ slots,
                                             const float* __restrict__ pos,
                                             const float* __restrict__ W1,
                                             const float* __restrict__ b1) {
    __shared__ float As[16][68];
    __shared__ float Bs[16][68];
    const int tid = threadIdx.x;
    const int m0 = blockIdx.x * 64, n0 = blockIdx.y * 64;
    const int tx = tid & 15, ty = tid >> 4;
    const int lm = tid >> 2, kq = tid & 3;
    const int bk = tid >> 4, bn = tid & 15;
    const int rm = m0 + lm;
    const float* arow = (rm < 1024) ? (slots + (size_t)rm * SD)
                                    : (pos + (size_t)(rm - 1024) * SD);
    float acc[4][4] = {};
    for (int kc = 0; kc < 16; kc++) {
        const int k0 = kc * 16;
        float4 av = *(const float4*)(arow + k0 + kq * 4);
        float4 bv = *(const float4*)(W1 + (size_t)(k0 + bk) * SD + n0 + bn * 4);
        __syncthreads();
        As[kq * 4 + 0][lm] = av.x; As[kq * 4 + 1][lm] = av.y;
        As[kq * 4 + 2][lm] = av.z; As[kq * 4 + 3][lm] = av.w;
        *(float4*)&Bs[bk][bn * 4] = bv;
        __syncthreads();
#pragma unroll
        for (int kk = 0; kk < 16; kk++) {
            float4 a4 = *(const float4*)&As[kk][ty * 4];
            float4 b4 = *(const float4*)&Bs[kk][tx * 4];
            float aa[4] = {a4.x, a4.y, a4.z, a4.w};
            float bb[4] = {b4.x, b4.y, b4.z, b4.w};
#pragma unroll
            for (int i = 0; i < 4; i++)
#pragma unroll
                for (int j = 0; j < 4; j++) acc[i][j] += aa[i] * bb[j];
        }
    }
    float4 b1v = *(const float4*)(b1 + n0 + tx * 4);
    float badd[4] = {b1v.x, b1v.y, b1v.z, b1v.w};
#pragma unroll
    for (int i = 0; i < 4; i++) {
        int m = m0 + ty * 4 + i;
        if (m < 1024) {
            *(float4*)(g_S + (size_t)m * SD + n0 + tx * 4) =
                make_float4(acc[i][0], acc[i][1], acc[i][2], acc[i][3]);
        } else {
            *(float4*)(g_P + (size_t)(m - 1024) * SD + n0 + tx * 4) =
                make_float4(acc[i][0] + badd[0], acc[i][1] + badd[1],
                            acc[i][2] + badd[2], acc[i][3] + badd[3]);
        }
    }
}

// ---------------------------------------------------------------------------
// K2b: W2 [K,N] -> g_W2h [N,K] as half (32x32 smem transpose)
// ---------------------------------------------------------------------------
__global__ void __launch_bounds__(256) k_w2h(const float* __restrict__ W2) {
    __shared__ float t[32][33];
    int k0 = blockIdx.x * 32, n0 = blockIdx.y * 32;
    int x = threadIdx.x & 31, y = threadIdx.x >> 5;   // 32 x 8
#pragma unroll
    for (int i = 0; i < 32; i += 8)
        t[y + i][x] = W2[(size_t)(k0 + y + i) * SD + n0 + x];
    __syncthreads();
#pragma unroll
    for (int i = 0; i < 32; i += 8)
        g_W2h[(size_t)(n0 + y + i) * SD + k0 + x] = __float2half_rn(t[x][y + i]);
}

// ---------------------------------------------------------------------------
// K3: fused gather + ReLU + GEMM2 with fp16 mma.sync m16n8k16, fp32 accum.
// CTA = 128(M=f) x 128(N), 8 warps = 4(M) x 2(N), warp tile 32x64.
// K=256 in 8 stages of 32 (2 k16 subtiles each).
// A built on the fly: half(relu(S[b,idx[f],:] + P[f,:])), fragment-native smem.
// B = g_W2h slice, fragment-native smem. Epilogue adds b2, fp32 out.
// ---------------------------------------------------------------------------
__global__ void __launch_bounds__(256, 2) k_main(const float* __restrict__ b2,
                                                 float* __restrict__ out) {
    // A frag: [mi(8)][ks16(2)][reg(4)][lane + pad] stride 34 (even, for uint2 ST)
    __shared__ uint32_t A_sm[8 * 2 * 4 * 34];      // 8704 B
    // B frag: [ni(16)][ks16(2)][reg(2)][lane(32)]
    __shared__ uint32_t B_sm[16 * 2 * 2 * 32];     // 8192 B
    __shared__ int   idx_sm[128];
    __shared__ float b2_sm[128];

    const int tid  = threadIdx.x;
    const int lane = tid & 31, wid = tid >> 5;
    const int wm = wid & 3, wn = wid >> 2;          // 4 x 2 warp grid
    const int nt = blockIdx.x, ft = blockIdx.y, b = blockIdx.z;
    const int f0 = ft * 128, n0 = nt * 128;

    if (tid < 128) {
        idx_sm[tid] = g_idx[b * FS + f0 + tid];
        b2_sm[tid]  = b2[n0 + tid];
    }

    const float* Sb = g_S + (size_t)b * NS * SD;

    float c[2][8][4];
#pragma unroll
    for (int m = 0; m < 2; m++)
#pragma unroll
        for (int n = 0; n < 8; n++)
#pragma unroll
            for (int k = 0; k < 4; k++) c[m][n][k] = 0.f;

#pragma unroll 1
    for (int kt = 0; kt < 8; kt++) {
        const int k0 = kt * 32;
        __syncthreads();   // previous stage's mma done reading A_sm/B_sm

        // --- B build: 128 n-rows x 32 k (half), 16B stores in fragment order
#pragma unroll
        for (int j = 0; j < 2; j++) {
            int v = j * 256 + tid;
            int n = v >> 2, cq = v & 3;              // n 0..127, cq: 8-k chunk
            uint4 w = *(const uint4*)(g_W2h + (size_t)(n0 + n) * SD + k0 + cq * 8);
            int ks16 = cq >> 1, reg = cq & 1;
            int g = n & 7, ni = n >> 3;
            *(uint4*)&B_sm[(((ni * 2 + ks16) * 2 + reg) << 5) + g * 4] = w;
        }

        // --- A build: relu(S[idx] + P) -> half2, fragment order (8B stores)
#pragma unroll
        for (int q = 0; q < 4; q++) {
            int v = q * 256 + tid;
            int r = v >> 3, cg = v & 7;              // row 0..127, 4-k group
            float4 p = *(const float4*)(g_P + (size_t)(f0 + r) * SD + k0 + cg * 4);
            int irow = idx_sm[r];
            float4 s = *(const float4*)(Sb + (size_t)irow * SD + k0 + cg * 4);
            __half2 h01 = __floats2half2_rn(fmaxf(p.x + s.x, 0.f), fmaxf(p.y + s.y, 0.f));
            __half2 h23 = __floats2half2_rn(fmaxf(p.z + s.z, 0.f), fmaxf(p.w + s.w, 0.f));
            int ks16 = cg >> 2, kbit = (cg & 3) >> 1, t0 = (cg & 1) * 2;
            int rr = r & 15, mi = r >> 4;
            int g = rr & 7, hi = rr >> 3;
            int reg = hi + 2 * kbit;
            int idx = ((mi * 2 + ks16) * 4 + reg) * 34 + g * 4 + t0;
            *(uint2*)&A_sm[idx] = make_uint2(*(uint32_t*)&h01, *(uint32_t*)&h23);
        }
        __syncthreads();   // A_sm / B_sm ready

        // --- MMA: 2 k16 subtiles x 2 m-frags x 8 n-frags
#pragma unroll
        for (int ks = 0; ks < 2; ks++) {
            uint32_t a[2][4];
#pragma unroll
            for (int m = 0; m < 2; m++) {
                int mi = wm * 2 + m;
#pragma unroll
                for (int rg = 0; rg < 4; rg++)
                    a[m][rg] = A_sm[((mi * 2 + ks) * 4 + rg) * 34 + lane];
            }
#pragma unroll
            for (int nf = 0; nf < 8; nf++) {
                int ni = wn * 8 + nf;
                uint32_t b0 = B_sm[(((ni * 2 + ks) * 2 + 0) << 5) + lane];
                uint32_t b1 = B_sm[(((ni * 2 + ks) * 2 + 1) << 5) + lane];
                mma_f16(c[0][nf], a[0], b0, b1);
                mma_f16(c[1][nf], a[1], b0, b1);
            }
        }
    }

    // --- epilogue: add b2, store fp32 (float2 = full sectors)
    const int g = lane >> 2, cc = (lane & 3) * 2;
#pragma unroll
    for (int m = 0; m < 2; m++) {
        int rbase = f0 + wm * 32 + m * 16 + g;
#pragma unroll
        for (int nf = 0; nf < 8; nf++) {
            int coll = wn * 64 + nf * 8 + cc;
            float bx = b2_sm[coll], by = b2_sm[coll + 1];
            size_t o0 = ((size_t)(b * FS + rbase)) * SD + n0 + coll;
            size_t o1 = ((size_t)(b * FS + rbase + 8)) * SD + n0 + coll;
            *(float2*)(out + o0) = make_float2(c[m][nf][0] + bx, c[m][nf][1] + by);
            *(float2*)(out + o1) = make_float2(c[m][nf][2] + bx, c[m][nf][3] + by);
        }
    }
}

// ---------------------------------------------------------------------------
extern "C" void kernel_launch(void* const* d_in, const int* in_sizes, int n_in,
                              void* d_out, int out_size) {
    const float* slots = (const float*)d_in[0];
    const float* mask  = (const float*)d_in[1];
    const float* pos   = (const float*)d_in[2];
    const float* W1    = (const float*)d_in[3];
    const float* b1    = (const float*)d_in[4];
    const float* W2    = (const float*)d_in[5];
    const float* b2    = (const float*)d_in[6];
    float* out = (float*)d_out;

    k_argmax<<<(B_SZ * FS) / 256, 256>>>(mask);
    k_pre<<<dim3(80, 4), 256>>>(slots, pos, W1, b1);
    k_w2h<<<dim3(8, 8), 256>>>(W2);
    k_main<<<dim3(2, 32, 64), 256>>>(b2, out);
}

// round 10
// speedup vs baseline: 2.1979x; 1.2078x over previous
#include <cuda_runtime.h>
#include <cuda_fp16.h>
#include <cstdint>

#define B_SZ 64
#define NS   16
#define SD   256
#define FS   4096

// scratch: S = slots@W1 (1MB), P = pos@W1 + b1 (4MB), idx (1MB), W2^T half (128KB)
static __device__ float  g_S[B_SZ * NS * SD];
static __device__ float  g_P[FS * SD];
static __device__ int    g_idx[B_SZ * FS];
static __device__ __half g_W2h[SD * SD];   // [n][k]

__device__ __forceinline__ void mma_f16(float* c, const uint32_t* a, uint32_t b0, uint32_t b1) {
    asm volatile(
        "mma.sync.aligned.m16n8k16.row.col.f32.f16.f16.f32 "
        "{%0,%1,%2,%3}, {%4,%5,%6,%7}, {%8,%9}, {%0,%1,%2,%3};"
        : "+f"(c[0]), "+f"(c[1]), "+f"(c[2]), "+f"(c[3])
        : "r"(a[0]), "r"(a[1]), "r"(a[2]), "r"(a[3]), "r"(b0), "r"(b1));
}

// ---------------------------------------------------------------------------
// K1: argmax over slot axis. mask[b, s, f] -> idx[b, f] (first max, matches jnp)
// ---------------------------------------------------------------------------
__global__ void k_argmax(const float* __restrict__ mask) {
    int t = blockIdx.x * blockDim.x + threadIdx.x;
    int b = t >> 12, f = t & (FS - 1);
    const float* mp = mask + (size_t)b * NS * FS + f;
    float best = mp[0];
    int bi = 0;
#pragma unroll
    for (int s = 1; s < NS; s++) {
        float v = mp[(size_t)s * FS];
        if (v > best) { best = v; bi = s; }
    }
    g_idx[t] = bi;
}

// ---------------------------------------------------------------------------
// K2: S = slots@W1 ; P = pos@W1 + b1  (fp32 exact, 64x64 tiles)
// ---------------------------------------------------------------------------
__global__ void __launch_bounds__(256) k_pre(const float* __restrict__ slots,
                                             const float* __restrict__ pos,
                                             const float* __restrict__ W1,
                                             const float* __restrict__ b1) {
    __shared__ float As[16][68];
    __shared__ float Bs[16][68];
    const int tid = threadIdx.x;
    const int m0 = blockIdx.x * 64, n0 = blockIdx.y * 64;
    const int tx = tid & 15, ty = tid >> 4;
    const int lm = tid >> 2, kq = tid & 3;
    const int bk = tid >> 4, bn = tid & 15;
    const int rm = m0 + lm;
    const float* arow = (rm < 1024) ? (slots + (size_t)rm * SD)
                                    : (pos + (size_t)(rm - 1024) * SD);
    float acc[4][4] = {};
    for (int kc = 0; kc < 16; kc++) {
        const int k0 = kc * 16;
        float4 av = *(const float4*)(arow + k0 + kq * 4);
        float4 bv = *(const float4*)(W1 + (size_t)(k0 + bk) * SD + n0 + bn * 4);
        __syncthreads();
        As[kq * 4 + 0][lm] = av.x; As[kq * 4 + 1][lm] = av.y;
        As[kq * 4 + 2][lm] = av.z; As[kq * 4 + 3][lm] = av.w;
        *(float4*)&Bs[bk][bn * 4] = bv;
        __syncthreads();
#pragma unroll
        for (int kk = 0; kk < 16; kk++) {
            float4 a4 = *(const float4*)&As[kk][ty * 4];
            float4 b4 = *(const float4*)&Bs[kk][tx * 4];
            float aa[4] = {a4.x, a4.y, a4.z, a4.w};
            float bb[4] = {b4.x, b4.y, b4.z, b4.w};
#pragma unroll
            for (int i = 0; i < 4; i++)
#pragma unroll
                for (int j = 0; j < 4; j++) acc[i][j] += aa[i] * bb[j];
        }
    }
    float4 b1v = *(const float4*)(b1 + n0 + tx * 4);
    float badd[4] = {b1v.x, b1v.y, b1v.z, b1v.w};
#pragma unroll
    for (int i = 0; i < 4; i++) {
        int m = m0 + ty * 4 + i;
        if (m < 1024) {
            *(float4*)(g_S + (size_t)m * SD + n0 + tx * 4) =
                make_float4(acc[i][0], acc[i][1], acc[i][2], acc[i][3]);
        } else {
            *(float4*)(g_P + (size_t)(m - 1024) * SD + n0 + tx * 4) =
                make_float4(acc[i][0] + badd[0], acc[i][1] + badd[1],
                            acc[i][2] + badd[2], acc[i][3] + badd[3]);
        }
    }
}

// ---------------------------------------------------------------------------
// K2b: W2 [K,N] -> g_W2h [N,K] as half (32x32 smem transpose)
// ---------------------------------------------------------------------------
__global__ void __launch_bounds__(256) k_w2h(const float* __restrict__ W2) {
    __shared__ float t[32][33];
    int k0 = blockIdx.x * 32, n0 = blockIdx.y * 32;
    int x = threadIdx.x & 31, y = threadIdx.x >> 5;   // 32 x 8
#pragma unroll
    for (int i = 0; i < 32; i += 8)
        t[y + i][x] = W2[(size_t)(k0 + y + i) * SD + n0 + x];
    __syncthreads();
#pragma unroll
    for (int i = 0; i < 32; i += 8)
        g_W2h[(size_t)(n0 + y + i) * SD + k0 + x] = __float2half_rn(t[x][y + i]);
}

// ---------------------------------------------------------------------------
// K3: fused gather + ReLU + GEMM2, fp16 mma.sync m16n8k16, fp32 accum.
// CTA = 128(M=f) x 256(N, full), 512 threads = 16 warps (4m x 4n),
// warp tile 32x64. K=256 in 8 stages of 32, double-buffered + pipelined:
//   sync; LDG(kt+1)->regs; MMA(kt); STS(kt+1). One barrier per stage.
// A frag stride 36 (16B-aligned octs -> STS.128); B interleaved (b0,b1) -> LDS.64.
// ---------------------------------------------------------------------------
#define A_WORDS (8 * 2 * 4 * 36)     // 2304 words / buf
#define B_WORDS (32 * 2 * 64)        // 4096 words / buf
#define SMEM_BYTES (2 * A_WORDS * 4 + 2 * B_WORDS * 4 + 128 * 4 + 256 * 4)

__global__ void __launch_bounds__(512, 1) k_main(const float* __restrict__ b2,
                                                 float* __restrict__ out) {
    extern __shared__ uint32_t sm[];
    uint32_t* Asm   = sm;                               // 2 bufs
    uint32_t* Bsm   = sm + 2 * A_WORDS;                 // 2 bufs
    int*      idx_s = (int*)(sm + 2 * A_WORDS + 2 * B_WORDS);
    float*    b2_s  = (float*)(idx_s + 128);

    const int tid  = threadIdx.x;
    const int lane = tid & 31, wid = tid >> 5;
    const int wm = wid & 3, wn = wid >> 2;              // 4 x 4 warp grid
    const int ft = blockIdx.x, b = blockIdx.y;
    const int f0 = ft * 128;

    if (tid < 128) idx_s[tid] = g_idx[b * FS + f0 + tid];
    if (tid < 256) b2_s[tid]  = b2[tid];
    __syncthreads();

    // --- per-thread fixed roles ---
    // A build: one k-oct per thread: r = tid>>2 (row), u = tid&3 (oct)
    const int ar = tid >> 2, au = tid & 3;
    const float* Sb = g_S + (size_t)b * NS * SD;
    const float* pA = g_P + (size_t)(f0 + ar) * SD + au * 8;
    const float* sA = Sb + (size_t)idx_s[ar] * SD + au * 8;
    // A store slot: words ((mi*2+ks16)*4+reg)*36 + g*4
    const int arr = ar & 15, ami = ar >> 4, ag = arr & 7, ahi = arr >> 3;
    const uint32_t aoff = (uint32_t)(((ami * 2 + (au >> 1)) * 4 + ahi + 2 * (au & 1)) * 36 + ag * 4);
    // B build: n = tid>>1, ks = tid&1
    const int bn = tid >> 1, bks = tid & 1;
    const __half* pB = g_W2h + (size_t)bn * SD + bks * 16;
    const uint32_t boff = (uint32_t)(((bn >> 3) * 2 + bks) * 64 + (bn & 7) * 8);

    float c[2][8][4];
#pragma unroll
    for (int m = 0; m < 2; m++)
#pragma unroll
        for (int n = 0; n < 8; n++)
#pragma unroll
            for (int k = 0; k < 4; k++) c[m][n][k] = 0.f;

    // --- prologue: stage 0 load + store ---
    float4 p0 = *(const float4*)(pA);
    float4 p1 = *(const float4*)(pA + 4);
    float4 s0 = *(const float4*)(sA);
    float4 s1 = *(const float4*)(sA + 4);
    uint4  w0 = *(const uint4*)(pB);
    uint4  w1 = *(const uint4*)(pB + 8);
    {
        __half2 h0 = __floats2half2_rn(fmaxf(p0.x + s0.x, 0.f), fmaxf(p0.y + s0.y, 0.f));
        __half2 h1 = __floats2half2_rn(fmaxf(p0.z + s0.z, 0.f), fmaxf(p0.w + s0.w, 0.f));
        __half2 h2 = __floats2half2_rn(fmaxf(p1.x + s1.x, 0.f), fmaxf(p1.y + s1.y, 0.f));
        __half2 h3 = __floats2half2_rn(fmaxf(p1.z + s1.z, 0.f), fmaxf(p1.w + s1.w, 0.f));
        uint4* dst = (uint4*)&Asm[aoff];
        *dst = make_uint4(*(uint32_t*)&h0, *(uint32_t*)&h1, *(uint32_t*)&h2, *(uint32_t*)&h3);
        uint4* bd = (uint4*)&Bsm[boff];
        bd[0] = make_uint4(w0.x, w1.x, w0.y, w1.y);
        bd[1] = make_uint4(w0.z, w1.z, w0.w, w1.w);
    }

#pragma unroll 1
    for (int kt = 0; kt < 8; kt++) {
        __syncthreads();   // STS of stage kt visible to all
        const uint32_t* Ab = Asm + (kt & 1) * A_WORDS;
        const uint32_t* Bb = Bsm + (kt & 1) * B_WORDS;

        // prefetch stage kt+1 into registers (overlaps with MMA below)
        if (kt < 7) {
            const int k1 = (kt + 1) * 32;
            p0 = *(const float4*)(pA + k1);
            p1 = *(const float4*)(pA + k1 + 4);
            s0 = *(const float4*)(sA + k1);
            s1 = *(const float4*)(sA + k1 + 4);
            w0 = *(const uint4*)(pB + k1);
            w1 = *(const uint4*)(pB + k1 + 8);
        }

        // --- MMA: 2 k16 subtiles x 2 m-frags x 8 n-frags ---
#pragma unroll
        for (int ks = 0; ks < 2; ks++) {
            uint32_t a[2][4];
#pragma unroll
            for (int m = 0; m < 2; m++) {
                int mi = wm * 2 + m;
#pragma unroll
                for (int rg = 0; rg < 4; rg++)
                    a[m][rg] = Ab[((mi * 2 + ks) * 4 + rg) * 36 + lane];
            }
#pragma unroll
            for (int nf = 0; nf < 8; nf++) {
                int ni = wn * 8 + nf;
                uint2 bb = *(const uint2*)&Bb[(ni * 2 + ks) * 64 + lane * 2];
                mma_f16(c[0][nf], a[0], bb.x, bb.y);
                mma_f16(c[1][nf], a[1], bb.x, bb.y);
            }
        }

        // --- store stage kt+1 to the other buffer ---
        if (kt < 7) {
            uint32_t* An = Asm + ((kt + 1) & 1) * A_WORDS;
            uint32_t* Bn = Bsm + ((kt + 1) & 1) * B_WORDS;
            __half2 h0 = __floats2half2_rn(fmaxf(p0.x + s0.x, 0.f), fmaxf(p0.y + s0.y, 0.f));
            __half2 h1 = __floats2half2_rn(fmaxf(p0.z + s0.z, 0.f), fmaxf(p0.w + s0.w, 0.f));
            __half2 h2 = __floats2half2_rn(fmaxf(p1.x + s1.x, 0.f), fmaxf(p1.y + s1.y, 0.f));
            __half2 h3 = __floats2half2_rn(fmaxf(p1.z + s1.z, 0.f), fmaxf(p1.w + s1.w, 0.f));
            *(uint4*)&An[aoff] = make_uint4(*(uint32_t*)&h0, *(uint32_t*)&h1,
                                            *(uint32_t*)&h2, *(uint32_t*)&h3);
            uint4* bd = (uint4*)&Bn[boff];
            bd[0] = make_uint4(w0.x, w1.x, w0.y, w1.y);
            bd[1] = make_uint4(w0.z, w1.z, w0.w, w1.w);
        }
    }

    // --- epilogue: add b2, store fp32 (float2 = full sectors) ---
    const int g = lane >> 2, cc = (lane & 3) * 2;
#pragma unroll
    for (int m = 0; m < 2; m++) {
        int rbase = f0 + wm * 32 + m * 16 + g;
#pragma unroll
        for (int nf = 0; nf < 8; nf++) {
            int coll = wn * 64 + nf * 8 + cc;
            float bx = b2_s[coll], by = b2_s[coll + 1];
            size_t o0 = ((size_t)(b * FS + rbase)) * SD + coll;
            size_t o1 = ((size_t)(b * FS + rbase + 8)) * SD + coll;
            *(float2*)(out + o0) = make_float2(c[m][nf][0] + bx, c[m][nf][1] + by);
            *(float2*)(out + o1) = make_float2(c[m][nf][2] + bx, c[m][nf][3] + by);
        }
    }
}

// ---------------------------------------------------------------------------
extern "C" void kernel_launch(void* const* d_in, const int* in_sizes, int n_in,
                              void* d_out, int out_size) {
    const float* slots = (const float*)d_in[0];
    const float* mask  = (const float*)d_in[1];
    const float* pos   = (const float*)d_in[2];
    const float* W1    = (const float*)d_in[3];
    const float* b1    = (const float*)d_in[4];
    const float* W2    = (const float*)d_in[5];
    const float* b2    = (const float*)d_in[6];
    float* out = (float*)d_out;

    cudaFuncSetAttribute(k_main, cudaFuncAttributeMaxDynamicSharedMemorySize, SMEM_BYTES);

    k_argmax<<<(B_SZ * FS) / 256, 256>>>(mask);
    k_pre<<<dim3(80, 4), 256>>>(slots, pos, W1, b1);
    k_w2h<<<dim3(8, 8), 256>>>(W2);
    k_main<<<dim3(32, 64), 512, SMEM_BYTES>>>(b2, out);
}

// round 11
// speedup vs baseline: 2.4392x; 1.1098x over previous
#include <cuda_runtime.h>
#include <cuda_fp16.h>
#include <cstdint>

#define B_SZ 64
#define NS   16
#define SD   256
#define FS   4096

// scratch: S = slots@W1 (1MB), P = pos@W1 + b1 (4MB), idx (1MB),
//          W2 fragment-packed (128KB)
static __device__ float    g_S[B_SZ * NS * SD];
static __device__ float    g_P[FS * SD];
static __device__ int      g_idx[B_SZ * FS];
static __device__ uint32_t g_W2f[32 * 16 * 32 * 2];   // [ni][kt16][lane][2]

__device__ __forceinline__ void mma_f16(float* c, const uint32_t* a, uint32_t b0, uint32_t b1) {
    asm volatile(
        "mma.sync.aligned.m16n8k16.row.col.f32.f16.f16.f32 "
        "{%0,%1,%2,%3}, {%4,%5,%6,%7}, {%8,%9}, {%0,%1,%2,%3};"
        : "+f"(c[0]), "+f"(c[1]), "+f"(c[2]), "+f"(c[3])
        : "r"(a[0]), "r"(a[1]), "r"(a[2]), "r"(a[3]), "r"(b0), "r"(b1));
}

// ---------------------------------------------------------------------------
// K1: argmax over slot axis. mask[b, s, f] -> idx[b, f] (first max, matches jnp)
// ---------------------------------------------------------------------------
__global__ void k_argmax(const float* __restrict__ mask) {
    int t = blockIdx.x * blockDim.x + threadIdx.x;
    int b = t >> 12, f = t & (FS - 1);
    const float* mp = mask + (size_t)b * NS * FS + f;
    float best = mp[0];
    int bi = 0;
#pragma unroll
    for (int s = 1; s < NS; s++) {
        float v = mp[(size_t)s * FS];
        if (v > best) { best = v; bi = s; }
    }
    g_idx[t] = bi;
}

// ---------------------------------------------------------------------------
// K2: S = slots@W1 ; P = pos@W1 + b1  (fp32 exact, 64x64 tiles)
// ---------------------------------------------------------------------------
__global__ void __launch_bounds__(256) k_pre(const float* __restrict__ slots,
                                             const float* __restrict__ pos,
                                             const float* __restrict__ W1,
                                             const float* __restrict__ b1) {
    __shared__ float As[16][68];
    __shared__ float Bs[16][68];
    const int tid = threadIdx.x;
    const int m0 = blockIdx.x * 64, n0 = blockIdx.y * 64;
    const int tx = tid & 15, ty = tid >> 4;
    const int lm = tid >> 2, kq = tid & 3;
    const int bk = tid >> 4, bn = tid & 15;
    const int rm = m0 + lm;
    const float* arow = (rm < 1024) ? (slots + (size_t)rm * SD)
                                    : (pos + (size_t)(rm - 1024) * SD);
    float acc[4][4] = {};
    for (int kc = 0; kc < 16; kc++) {
        const int k0 = kc * 16;
        float4 av = *(const float4*)(arow + k0 + kq * 4);
        float4 bv = *(const float4*)(W1 + (size_t)(k0 + bk) * SD + n0 + bn * 4);
        __syncthreads();
        As[kq * 4 + 0][lm] = av.x; As[kq * 4 + 1][lm] = av.y;
        As[kq * 4 + 2][lm] = av.z; As[kq * 4 + 3][lm] = av.w;
        *(float4*)&Bs[bk][bn * 4] = bv;
        __syncthreads();
#pragma unroll
        for (int kk = 0; kk < 16; kk++) {
            float4 a4 = *(const float4*)&As[kk][ty * 4];
            float4 b4 = *(const float4*)&Bs[kk][tx * 4];
            float aa[4] = {a4.x, a4.y, a4.z, a4.w};
            float bb[4] = {b4.x, b4.y, b4.z, b4.w};
#pragma unroll
            for (int i = 0; i < 4; i++)
#pragma unroll
                for (int j = 0; j < 4; j++) acc[i][j] += aa[i] * bb[j];
        }
    }
    float4 b1v = *(const float4*)(b1 + n0 + tx * 4);
    float badd[4] = {b1v.x, b1v.y, b1v.z, b1v.w};
#pragma unroll
    for (int i = 0; i < 4; i++) {
        int m = m0 + ty * 4 + i;
        if (m < 1024) {
            *(float4*)(g_S + (size_t)m * SD + n0 + tx * 4) =
                make_float4(acc[i][0], acc[i][1], acc[i][2], acc[i][3]);
        } else {
            *(float4*)(g_P + (size_t)(m - 1024) * SD + n0 + tx * 4) =
                make_float4(acc[i][0] + badd[0], acc[i][1] + badd[1],
                            acc[i][2] + badd[2], acc[i][3] + badd[3]);
        }
    }
}

// ---------------------------------------------------------------------------
// K2b: pack W2 [K,N] into half fragments g_W2f[ni][kt16][lane][2]
//   b0 = (W2[k, n], W2[k+1, n]), b1 = (W2[k+8, n], W2[k+9, n])
//   with n = ni*8 + lane/4, k = kt16*16 + (lane%4)*2
// ---------------------------------------------------------------------------
__global__ void __launch_bounds__(256) k_w2f(const float* __restrict__ W2) {
    int t = blockIdx.x * 256 + threadIdx.x;     // 16384 tasks
    int lane = t & 31, kt = (t >> 5) & 15, ni = t >> 9;
    int n = ni * 8 + (lane >> 2);
    int k = kt * 16 + (lane & 3) * 2;
    __half2 b0 = __floats2half2_rn(W2[(size_t)k * SD + n], W2[(size_t)(k + 1) * SD + n]);
    __half2 b1 = __floats2half2_rn(W2[(size_t)(k + 8) * SD + n], W2[(size_t)(k + 9) * SD + n]);
    g_W2f[t * 2 + 0] = *(uint32_t*)&b0;
    g_W2f[t * 2 + 1] = *(uint32_t*)&b1;
}

// ---------------------------------------------------------------------------
// K3: fused gather + ReLU + GEMM2, fp16 mma.sync m16n8k16, fp32 accum.
// CTA = 128(M=f) x 256(N full), 256 threads = 8 warps (2 wm x 4 wn),
// warp tile 64x64. Whole-K A tile (128x256 half) built ONCE into smem in
// fragment order; then a sync-free mma loop over 16 k16 tiles with
// B fragments loaded directly from g_W2f (L1-resident, coalesced LDG.64).
// ---------------------------------------------------------------------------
#define ASTRIDE 34                       // words per fragment (32 lanes + pad)
#define A_WORDS (8 * 16 * 4 * ASTRIDE)   // 17408 words = 69632 B
#define SMEM_BYTES (A_WORDS * 4 + 128 * 4 + 256 * 4)

__global__ void __launch_bounds__(256, 1) k_main(const float* __restrict__ b2,
                                                 float* __restrict__ out) {
    extern __shared__ uint32_t sm[];
    uint32_t* Asm   = sm;
    int*      idx_s = (int*)(sm + A_WORDS);
    float*    b2_s  = (float*)(idx_s + 128);

    const int tid  = threadIdx.x;
    const int lane = tid & 31, wid = tid >> 5;
    const int wm = wid & 1, wn = wid >> 1;          // 2 x 4 warp grid
    const int ft = blockIdx.x, b = blockIdx.y;
    const int f0 = ft * 128;

    if (tid < 128) idx_s[tid] = g_idx[b * FS + f0 + tid];
    b2_s[tid] = b2[tid];                            // 256 threads = 256 cols
    __syncthreads();

    const float* Sb = g_S + (size_t)b * NS * SD;

    // --- build A tile (whole K) in fragment order: 4096 octs, 16/thread ---
    // task t: row r = t>>5, k-oct au = t&31 (k = au*8 .. au*8+7)
#pragma unroll 2
    for (int it = 0; it < 16; it++) {
        int t = it * 256 + tid;
        int r = t >> 5, au = t & 31;
        const float* pP = g_P + (size_t)(f0 + r) * SD + au * 8;
        const float* pS = Sb + (size_t)idx_s[r] * SD + au * 8;
        float4 p0 = *(const float4*)(pP);
        float4 p1 = *(const float4*)(pP + 4);
        float4 s0 = *(const float4*)(pS);
        float4 s1 = *(const float4*)(pS + 4);
        __half2 h0 = __floats2half2_rn(fmaxf(p0.x + s0.x, 0.f), fmaxf(p0.y + s0.y, 0.f));
        __half2 h1 = __floats2half2_rn(fmaxf(p0.z + s0.z, 0.f), fmaxf(p0.w + s0.w, 0.f));
        __half2 h2 = __floats2half2_rn(fmaxf(p1.x + s1.x, 0.f), fmaxf(p1.y + s1.y, 0.f));
        __half2 h3 = __floats2half2_rn(fmaxf(p1.z + s1.z, 0.f), fmaxf(p1.w + s1.w, 0.f));
        int ks16 = au >> 1, kbit = au & 1;
        int arr = r & 15, mi = r >> 4, ag = arr & 7, ahi = arr >> 3;
        int reg = ahi + 2 * kbit;
        uint32_t base = (uint32_t)(((mi * 16 + ks16) * 4 + reg) * ASTRIDE + ag * 4);
        *(uint2*)&Asm[base + 0] = make_uint2(*(uint32_t*)&h0, *(uint32_t*)&h1);
        *(uint2*)&Asm[base + 2] = make_uint2(*(uint32_t*)&h2, *(uint32_t*)&h3);
    }
    __syncthreads();

    // --- accumulators: warp tile 64(m) x 64(n) ---
    float c[4][8][4];
#pragma unroll
    for (int m = 0; m < 4; m++)
#pragma unroll
        for (int n = 0; n < 8; n++)
#pragma unroll
            for (int k = 0; k < 4; k++) c[m][n][k] = 0.f;

    // B fragment base for this warp: frags (ni = wn*8+nf, kt)
    const uint32_t* Bf = g_W2f + ((size_t)(wn * 8) * 16 * 64) + lane * 2;

    // --- sync-free mma loop over 16 k16 tiles ---
#pragma unroll 1
    for (int kt = 0; kt < 16; kt++) {
        uint32_t a[4][4];
#pragma unroll
        for (int m = 0; m < 4; m++) {
            int mi = wm * 4 + m;
#pragma unroll
            for (int rg = 0; rg < 4; rg++)
                a[m][rg] = Asm[((mi * 16 + kt) * 4 + rg) * ASTRIDE + lane];
        }
        const uint32_t* Bk = Bf + kt * 64;
#pragma unroll
        for (int nf = 0; nf < 8; nf++) {
            uint2 bb = *(const uint2*)(Bk + nf * 1024);   // frag stride 16*64 words
            mma_f16(c[0][nf], a[0], bb.x, bb.y);
            mma_f16(c[1][nf], a[1], bb.x, bb.y);
            mma_f16(c[2][nf], a[2], bb.x, bb.y);
            mma_f16(c[3][nf], a[3], bb.x, bb.y);
        }
    }

    // --- epilogue: add b2, store fp32 (float2 = full sectors) ---
    const int g = lane >> 2, cc = (lane & 3) * 2;
#pragma unroll
    for (int m = 0; m < 4; m++) {
        int rbase = f0 + wm * 64 + m * 16 + g;
#pragma unroll
        for (int nf = 0; nf < 8; nf++) {
            int coll = wn * 64 + nf * 8 + cc;
            float bx = b2_s[coll], by = b2_s[coll + 1];
            size_t o0 = ((size_t)(b * FS + rbase)) * SD + coll;
            size_t o1 = ((size_t)(b * FS + rbase + 8)) * SD + coll;
            *(float2*)(out + o0) = make_float2(c[m][nf][0] + bx, c[m][nf][1] + by);
            *(float2*)(out + o1) = make_float2(c[m][nf][2] + bx, c[m][nf][3] + by);
        }
    }
}

// ---------------------------------------------------------------------------
extern "C" void kernel_launch(void* const* d_in, const int* in_sizes, int n_in,
                              void* d_out, int out_size) {
    const float* slots = (const float*)d_in[0];
    const float* mask  = (const float*)d_in[1];
    const float* pos   = (const float*)d_in[2];
    const float* W1    = (const float*)d_in[3];
    const float* b1    = (const float*)d_in[4];
    const float* W2    = (const float*)d_in[5];
    const float* b2    = (const float*)d_in[6];
    float* out = (float*)d_out;

    cudaFuncSetAttribute(k_main, cudaFuncAttributeMaxDynamicSharedMemorySize, SMEM_BYTES);

    k_argmax<<<(B_SZ * FS) / 256, 256>>>(mask);
    k_pre<<<dim3(80, 4), 256>>>(slots, pos, W1, b1);
    k_w2f<<<64, 256>>>(W2);
    k_main<<<dim3(32, 64), 256, SMEM_BYTES>>>(b2, out);
}